// round 13
// baseline (speedup 1.0000x reference)
#include <cuda_runtime.h>
#include <cuda_bf16.h>
#include <cstdint>

// Problem shape (fixed by the reference)
#define BB 8
#define CC 16
#define HH 512
#define WW 1024

// One thread = 8 consecutive-w pixels (2 float4 spans). disp/index/weight
// computed once, shared across all 16 channels. Per channel iteration:
// 16 batched scalar gathers (default caching — R7 proved .cs costs 20us)
// + two aligned float4 stores. Doubling per-thread work vs the 4px baseline
// (91.2us, DRAM 68%) halves fixed overhead and doubles per-warp MLP; channel
// unroll kept at 2 to bound register pressure. If this regresses (occ < ~25%
// starving the memory pipe), the 4px R11 kernel is the final answer.
__global__ __launch_bounds__(256) void warp_disp_kernel(
    const float* __restrict__ input,   // [B,C,H,W]
    const float* __restrict__ disp,    // [B,1,H,W]
    float* __restrict__ out)           // [B,C,H,W]
{
    const int tid = blockIdx.x * blockDim.x + threadIdx.x;   // 512K threads
    const int w0  = (tid * 8) & (WW - 1);                    // 0..1016, step 8
    const int bh  = tid / (WW / 8);                          // b*H + h
    const int h   = bh & (HH - 1);
    const int b   = bh >> 9;                                 // /HH

    // disp layout [B,1,H,W] == [B*H*W]; two aligned float4 loads
    const float4 dA = __ldg((const float4*)(disp + bh * WW + w0));
    const float4 dB = __ldg((const float4*)(disp + bh * WW + w0) + 1);

    int   x0[8], x1[8];
    float wl[8], wr[8];
    const float dvals[8] = {dA.x, dA.y, dA.z, dA.w, dB.x, dB.y, dB.z, dB.w};
    #pragma unroll
    for (int i = 0; i < 8; ++i) {
        float x = (float)(w0 + i) + dvals[i];
        x = fminf(fmaxf(x, 0.0f), (float)(WW - 1));
        const float x0f = floorf(x);
        const float x1f = fminf(x0f + 1.0f, (float)(WW - 1));
        x0[i] = (int)x0f;
        x1[i] = (int)x1f;
        wl[i] = x1f - x;          // note: NOT 1-wr; both 0 at the right clamp
        wr[i] = x - x0f;
    }

    // All element offsets fit in int32 (64M elements max).
    const int row_base = (b * CC * HH + h) * WW;
    const float* in_row = input + row_base;
    float*      out_row = out   + row_base + w0;
    const int cstride = HH * WW;   // 524288

    #pragma unroll 2
    for (int c = 0; c < CC; ++c) {
        const float* rc = in_row + c * cstride;
        // Batch all 16 gathers ahead of the FMA/store chain (max MLP per iter).
        float pl[8], pr[8];
        #pragma unroll
        for (int i = 0; i < 8; ++i) pl[i] = __ldg(rc + x0[i]);
        #pragma unroll
        for (int i = 0; i < 8; ++i) pr[i] = __ldg(rc + x1[i]);
        float4 rA, rB;
        rA.x = wl[0] * pl[0] + wr[0] * pr[0];
        rA.y = wl[1] * pl[1] + wr[1] * pr[1];
        rA.z = wl[2] * pl[2] + wr[2] * pr[2];
        rA.w = wl[3] * pl[3] + wr[3] * pr[3];
        rB.x = wl[4] * pl[4] + wr[4] * pr[4];
        rB.y = wl[5] * pl[5] + wr[5] * pr[5];
        rB.z = wl[6] * pl[6] + wr[6] * pr[6];
        rB.w = wl[7] * pl[7] + wr[7] * pr[7];
        *(float4*)(out_row + c * cstride)     = rA;
        *((float4*)(out_row + c * cstride) + 1) = rB;
    }
}

extern "C" void kernel_launch(void* const* d_in, const int* in_sizes, int n_in,
                              void* d_out, int out_size) {
    const float* input = (const float*)d_in[0];
    const float* disp  = (const float*)d_in[1];
    float* out = (float*)d_out;

    const int n_threads = BB * HH * (WW / 8);   // 524,288
    const int threads = 256;
    warp_disp_kernel<<<n_threads / threads, threads>>>(input, disp, out);
}

// round 14
// speedup vs baseline: 1.2528x; 1.2528x over previous
#include <cuda_runtime.h>
#include <cuda_bf16.h>
#include <cstdint>

// Problem shape (fixed by the reference)
#define BB 8
#define CC 16
#define HH 512
#define WW 1024

// FINAL — measured optimum across 7 profiled variants (91us ncu, 5.57TB/s,
// reproduced twice). One thread = 4 consecutive-w pixels; disp/index/weight
// computed once and shared across all 16 channels; per channel-iter: 8 batched
// scalar gathers (default caching; .cs cost 20us in R7) + one aligned float4
// store. Falsified levers: occupancy 46->87% (R5/R9 flat), L1 wavefronts
// 67->38% (R9 worse), L2 streaming (R7 -20us), pure-stream smem staging (R10
// flat), 8px/thread (R13: L1 wavefront explosion, -27us). Traffic is within
// 8% of the 554MB analytic floor; the kernel runs at the chip's practical
// ceiling for a 1:1 read:write HBM stream with data-dependent gathers.
__global__ __launch_bounds__(256) void warp_disp_kernel(
    const float* __restrict__ input,   // [B,C,H,W]
    const float* __restrict__ disp,    // [B,1,H,W]
    float* __restrict__ out)           // [B,C,H,W]
{
    const int tid = blockIdx.x * blockDim.x + threadIdx.x;   // 1M threads
    const int w0  = (tid * 4) & (WW - 1);                    // 0..1020, step 4
    const int bh  = tid / (WW / 4);                          // b*H + h
    const int h   = bh & (HH - 1);
    const int b   = bh >> 9;                                 // /HH

    // disp layout [B,1,H,W] == [B*H*W]; aligned float4 load
    const float4 d4 = __ldg((const float4*)(disp + bh * WW + w0));

    int   x0[4], x1[4];
    float wl[4], wr[4];
    const float dvals[4] = {d4.x, d4.y, d4.z, d4.w};
    #pragma unroll
    for (int i = 0; i < 4; ++i) {
        float x = (float)(w0 + i) + dvals[i];
        x = fminf(fmaxf(x, 0.0f), (float)(WW - 1));
        const float x0f = floorf(x);
        const float x1f = fminf(x0f + 1.0f, (float)(WW - 1));
        x0[i] = (int)x0f;
        x1[i] = (int)x1f;
        wl[i] = x1f - x;          // note: NOT 1-wr; both 0 at the right clamp
        wr[i] = x - x0f;
    }

    // All element offsets fit in int32 (64M elements max).
    const int row_base = (b * CC * HH + h) * WW;
    const float* in_row = input + row_base;
    float*      out_row = out   + row_base + w0;
    const int cstride = HH * WW;   // 524288

    #pragma unroll 4
    for (int c = 0; c < CC; ++c) {
        const float* rc = in_row + c * cstride;
        // Batch all 8 gathers ahead of the FMA/store chain (max MLP per iter).
        const float pl0 = __ldg(rc + x0[0]);
        const float pr0 = __ldg(rc + x1[0]);
        const float pl1 = __ldg(rc + x0[1]);
        const float pr1 = __ldg(rc + x1[1]);
        const float pl2 = __ldg(rc + x0[2]);
        const float pr2 = __ldg(rc + x1[2]);
        const float pl3 = __ldg(rc + x0[3]);
        const float pr3 = __ldg(rc + x1[3]);
        float4 r;
        r.x = wl[0] * pl0 + wr[0] * pr0;
        r.y = wl[1] * pl1 + wr[1] * pr1;
        r.z = wl[2] * pl2 + wr[2] * pr2;
        r.w = wl[3] * pl3 + wr[3] * pr3;
        *(float4*)(out_row + c * cstride) = r;
    }
}

extern "C" void kernel_launch(void* const* d_in, const int* in_sizes, int n_in,
                              void* d_out, int out_size) {
    const float* input = (const float*)d_in[0];
    const float* disp  = (const float*)d_in[1];
    float* out = (float*)d_out;

    const int n_threads = BB * HH * (WW / 4);   // 1,048,576
    const int threads = 256;
    warp_disp_kernel<<<n_threads / threads, threads>>>(input, disp, out);
}